// round 1
// baseline (speedup 1.0000x reference)
#include <cuda_runtime.h>
#include <math.h>

#define BB 8
#define NN 1024
#define CC 768
#define HH 12
#define ZZ 64
#define BH (BB*HH)
#define SCALE 0.125f

// ---------------- scratch (no allocations allowed) ----------------
__device__ float g_Q [BB*NN*CC];
__device__ float g_K [BB*NN*CC];
__device__ float g_U1[CC*CC];        // U1t[e][c] = sum_d Wp[e,d]*Wq[c,d]
__device__ float g_U2[CC*CC];        // U2t[e][c] = sum_d Wp[e,d]*Wk[c,d]
__device__ float g_Ck[BB*NN*CC];     // (A^T K) flattened  [b][t][h*64+z]
__device__ float g_Cq[BB*NN*CC];     // (A^T Q) flattened
__device__ float g_m [BH*NN];        // softmax row max
__device__ float g_il[BH*NN];        // softmax 1/row-sum

// =============================================================================
// Generic C = A(MxK) * B(NxK)^T, 128x128x8 tiles, 8x8 interleaved micro-tile
// =============================================================================
__global__ __launch_bounds__(256) void gemm_abt128(
    const float* __restrict__ A, const float* __restrict__ B,
    float* __restrict__ C, int M, int N, int K)
{
    __shared__ float As[128][9];
    __shared__ float Bs[128][9];
    const int tid = threadIdx.x;
    const int tx = tid & 15, ty = tid >> 4;
    const int m0 = blockIdx.x * 128, n0 = blockIdx.y * 128;
    const int lr = tid >> 1, lc = (tid & 1) << 2;

    float acc[8][8];
#pragma unroll
    for (int i = 0; i < 8; i++)
#pragma unroll
        for (int j = 0; j < 8; j++) acc[i][j] = 0.0f;

    for (int k0 = 0; k0 < K; k0 += 8) {
        float4 va = *reinterpret_cast<const float4*>(A + (size_t)(m0 + lr) * K + k0 + lc);
        float4 vb = *reinterpret_cast<const float4*>(B + (size_t)(n0 + lr) * K + k0 + lc);
        As[lr][lc] = va.x; As[lr][lc+1] = va.y; As[lr][lc+2] = va.z; As[lr][lc+3] = va.w;
        Bs[lr][lc] = vb.x; Bs[lr][lc+1] = vb.y; Bs[lr][lc+2] = vb.z; Bs[lr][lc+3] = vb.w;
        __syncthreads();
#pragma unroll
        for (int k = 0; k < 8; k++) {
            float a[8], b[8];
#pragma unroll
            for (int i = 0; i < 8; i++) a[i] = As[ty + i*16][k];
#pragma unroll
            for (int j = 0; j < 8; j++) b[j] = Bs[tx + j*16][k];
#pragma unroll
            for (int i = 0; i < 8; i++)
#pragma unroll
                for (int j = 0; j < 8; j++) acc[i][j] += a[i] * b[j];
        }
        __syncthreads();
    }
#pragma unroll
    for (int i = 0; i < 8; i++)
#pragma unroll
        for (int j = 0; j < 8; j++)
            C[(size_t)(m0 + ty + i*16) * N + n0 + tx + j*16] = acc[i][j];
}

// =============================================================================
// Small-tile version (64x64x16) for the 768x768 weight precompute GEMMs
// =============================================================================
__global__ __launch_bounds__(256) void gemm_abt64(
    const float* __restrict__ A, const float* __restrict__ B,
    float* __restrict__ C, int M, int N, int K)
{
    __shared__ float As[64][17];
    __shared__ float Bs[64][17];
    const int tid = threadIdx.x;
    const int tx = tid & 15, ty = tid >> 4;
    const int m0 = blockIdx.x * 64, n0 = blockIdx.y * 64;
    const int lr = tid >> 2, lc = (tid & 3) << 2;

    float acc[4][4];
#pragma unroll
    for (int i = 0; i < 4; i++)
#pragma unroll
        for (int j = 0; j < 4; j++) acc[i][j] = 0.0f;

    for (int k0 = 0; k0 < K; k0 += 16) {
        float4 va = *reinterpret_cast<const float4*>(A + (size_t)(m0 + lr) * K + k0 + lc);
        float4 vb = *reinterpret_cast<const float4*>(B + (size_t)(n0 + lr) * K + k0 + lc);
        As[lr][lc] = va.x; As[lr][lc+1] = va.y; As[lr][lc+2] = va.z; As[lr][lc+3] = va.w;
        Bs[lr][lc] = vb.x; Bs[lr][lc+1] = vb.y; Bs[lr][lc+2] = vb.z; Bs[lr][lc+3] = vb.w;
        __syncthreads();
#pragma unroll
        for (int k = 0; k < 16; k++) {
            float a[4], b[4];
#pragma unroll
            for (int i = 0; i < 4; i++) a[i] = As[ty + i*16][k];
#pragma unroll
            for (int j = 0; j < 4; j++) b[j] = Bs[tx + j*16][k];
#pragma unroll
            for (int i = 0; i < 4; i++)
#pragma unroll
                for (int j = 0; j < 4; j++) acc[i][j] += a[i] * b[j];
        }
        __syncthreads();
    }
#pragma unroll
    for (int i = 0; i < 4; i++)
#pragma unroll
        for (int j = 0; j < 4; j++)
            C[(size_t)(m0 + ty + i*16) * N + n0 + tx + j*16] = acc[i][j];
}

// =============================================================================
// Fused output: out = A1*B1^T + A2*B2^T + bias  (128x128x8 tiles)
// =============================================================================
__global__ __launch_bounds__(256) void gemm_dual128(
    const float* __restrict__ A1, const float* __restrict__ B1,
    const float* __restrict__ A2, const float* __restrict__ B2,
    const float* __restrict__ bias, float* __restrict__ C,
    int M, int N, int K)
{
    __shared__ float A1s[128][9], B1s[128][9], A2s[128][9], B2s[128][9];
    const int tid = threadIdx.x;
    const int tx = tid & 15, ty = tid >> 4;
    const int m0 = blockIdx.x * 128, n0 = blockIdx.y * 128;
    const int lr = tid >> 1, lc = (tid & 1) << 2;

    float acc[8][8];
#pragma unroll
    for (int i = 0; i < 8; i++)
#pragma unroll
        for (int j = 0; j < 8; j++) acc[i][j] = 0.0f;

    for (int k0 = 0; k0 < K; k0 += 8) {
        float4 v1 = *reinterpret_cast<const float4*>(A1 + (size_t)(m0 + lr) * K + k0 + lc);
        float4 w1 = *reinterpret_cast<const float4*>(B1 + (size_t)(n0 + lr) * K + k0 + lc);
        float4 v2 = *reinterpret_cast<const float4*>(A2 + (size_t)(m0 + lr) * K + k0 + lc);
        float4 w2 = *reinterpret_cast<const float4*>(B2 + (size_t)(n0 + lr) * K + k0 + lc);
        A1s[lr][lc] = v1.x; A1s[lr][lc+1] = v1.y; A1s[lr][lc+2] = v1.z; A1s[lr][lc+3] = v1.w;
        B1s[lr][lc] = w1.x; B1s[lr][lc+1] = w1.y; B1s[lr][lc+2] = w1.z; B1s[lr][lc+3] = w1.w;
        A2s[lr][lc] = v2.x; A2s[lr][lc+1] = v2.y; A2s[lr][lc+2] = v2.z; A2s[lr][lc+3] = v2.w;
        B2s[lr][lc] = w2.x; B2s[lr][lc+1] = w2.y; B2s[lr][lc+2] = w2.z; B2s[lr][lc+3] = w2.w;
        __syncthreads();
#pragma unroll
        for (int k = 0; k < 8; k++) {
            float a1[8], b1[8], a2[8], b2[8];
#pragma unroll
            for (int i = 0; i < 8; i++) { a1[i] = A1s[ty + i*16][k]; a2[i] = A2s[ty + i*16][k]; }
#pragma unroll
            for (int j = 0; j < 8; j++) { b1[j] = B1s[tx + j*16][k]; b2[j] = B2s[tx + j*16][k]; }
#pragma unroll
            for (int i = 0; i < 8; i++)
#pragma unroll
                for (int j = 0; j < 8; j++)
                    acc[i][j] += a1[i] * b1[j] + a2[i] * b2[j];
        }
        __syncthreads();
    }
#pragma unroll
    for (int i = 0; i < 8; i++)
#pragma unroll
        for (int j = 0; j < 8; j++)
            C[(size_t)(m0 + ty + i*16) * N + n0 + tx + j*16] =
                acc[i][j] + bias[n0 + tx + j*16];
}

// =============================================================================
// Pass A: per-row softmax stats m, 1/l over S = scale * Q K^T  (per b,h)
// Block: 64 q-rows, loops over all 1024 t in 64-tiles. 256 thr, 4x4 micro.
// =============================================================================
__global__ __launch_bounds__(256) void attn_stats()
{
    __shared__ float Qs[64][65];
    __shared__ float Ks[64][65];
    const int tid = threadIdx.x, tx = tid & 15, ty = tid >> 4;
    const int bh = blockIdx.y;
    const int b = bh / HH, h = bh - b * HH;
    const int q0 = blockIdx.x * 64;
    const float* Qbase = g_Q + (size_t)b * NN * CC + h * ZZ;
    const float* Kbase = g_K + (size_t)b * NN * CC + h * ZZ;

    for (int i = tid; i < 64 * 16; i += 256) {
        int r = i >> 4, c = (i & 15) << 2;
        float4 v = *reinterpret_cast<const float4*>(Qbase + (size_t)(q0 + r) * CC + c);
        Qs[r][c] = v.x; Qs[r][c+1] = v.y; Qs[r][c+2] = v.z; Qs[r][c+3] = v.w;
    }

    float rm[4], rl[4];
#pragma unroll
    for (int i = 0; i < 4; i++) { rm[i] = -INFINITY; rl[i] = 0.0f; }

    for (int t0 = 0; t0 < NN; t0 += 64) {
        for (int i = tid; i < 64 * 16; i += 256) {
            int r = i >> 4, c = (i & 15) << 2;
            float4 v = *reinterpret_cast<const float4*>(Kbase + (size_t)(t0 + r) * CC + c);
            Ks[r][c] = v.x; Ks[r][c+1] = v.y; Ks[r][c+2] = v.z; Ks[r][c+3] = v.w;
        }
        __syncthreads();

        float s[4][4];
#pragma unroll
        for (int i = 0; i < 4; i++)
#pragma unroll
            for (int j = 0; j < 4; j++) s[i][j] = 0.0f;
#pragma unroll 8
        for (int z = 0; z < 64; z++) {
            float a[4], bb[4];
#pragma unroll
            for (int i = 0; i < 4; i++) a[i] = Qs[ty + i*16][z];
#pragma unroll
            for (int j = 0; j < 4; j++) bb[j] = Ks[tx + j*16][z];
#pragma unroll
            for (int i = 0; i < 4; i++)
#pragma unroll
                for (int j = 0; j < 4; j++) s[i][j] += a[i] * bb[j];
        }

#pragma unroll
        for (int i = 0; i < 4; i++) {
            float tmax = s[i][0];
#pragma unroll
            for (int j = 1; j < 4; j++) tmax = fmaxf(tmax, s[i][j]);
            tmax *= SCALE;
#pragma unroll
            for (int o = 8; o > 0; o >>= 1)
                tmax = fmaxf(tmax, __shfl_xor_sync(0xffffffffu, tmax, o));
            float nm = fmaxf(rm[i], tmax);
            float ls = 0.0f;
#pragma unroll
            for (int j = 0; j < 4; j++) ls += __expf(s[i][j] * SCALE - nm);
#pragma unroll
            for (int o = 8; o > 0; o >>= 1)
                ls += __shfl_xor_sync(0xffffffffu, ls, o);
            rl[i] = rl[i] * __expf(rm[i] - nm) + ls;
            rm[i] = nm;
        }
        __syncthreads();
    }

    if (tx == 0) {
#pragma unroll
        for (int i = 0; i < 4; i++) {
            int q = bh * NN + q0 + ty + i * 16;
            g_m[q]  = rm[i];
            g_il[q] = 1.0f / rl[i];
        }
    }
}

// =============================================================================
// Pass B: Ck = A^T K, Cq = A^T Q  (per b,h; block owns a 64-wide t-tile,
// streams q in 32-row tiles, P tile staged through SMEM for the transpose)
// =============================================================================
__global__ __launch_bounds__(256) void attn_pass()
{
    __shared__ float Kt[64][65];
    __shared__ float Qq[32][65];
    __shared__ float Kq[32][65];
    __shared__ float Ps[32][65];
    __shared__ float ms[32], ils[32];
    const int tid = threadIdx.x, tx = tid & 15, ty = tid >> 4;
    const int bh = blockIdx.y;
    const int b = bh / HH, h = bh - b * HH;
    const int t0 = blockIdx.x * 64;
    const float* Qbase = g_Q + (size_t)b * NN * CC + h * ZZ;
    const float* Kbase = g_K + (size_t)b * NN * CC + h * ZZ;

    for (int i = tid; i < 64 * 16; i += 256) {
        int r = i >> 4, c = (i & 15) << 2;
        float4 v = *reinterpret_cast<const float4*>(Kbase + (size_t)(t0 + r) * CC + c);
        Kt[r][c] = v.x; Kt[r][c+1] = v.y; Kt[r][c+2] = v.z; Kt[r][c+3] = v.w;
    }

    float ck[4][4], cq[4][4];
#pragma unroll
    for (int i = 0; i < 4; i++)
#pragma unroll
        for (int j = 0; j < 4; j++) { ck[i][j] = 0.0f; cq[i][j] = 0.0f; }

    for (int q0 = 0; q0 < NN; q0 += 32) {
        for (int i = tid; i < 32 * 16; i += 256) {
            int r = i >> 4, c = (i & 15) << 2;
            float4 v = *reinterpret_cast<const float4*>(Qbase + (size_t)(q0 + r) * CC + c);
            float4 w = *reinterpret_cast<const float4*>(Kbase + (size_t)(q0 + r) * CC + c);
            Qq[r][c] = v.x; Qq[r][c+1] = v.y; Qq[r][c+2] = v.z; Qq[r][c+3] = v.w;
            Kq[r][c] = w.x; Kq[r][c+1] = w.y; Kq[r][c+2] = w.z; Kq[r][c+3] = w.w;
        }
        if (tid < 32) {
            ms[tid]  = g_m [bh * NN + q0 + tid];
            ils[tid] = g_il[bh * NN + q0 + tid];
        }
        __syncthreads();

        // S tile: 32 q x 64 t
        float s[2][4];
#pragma unroll
        for (int i = 0; i < 2; i++)
#pragma unroll
            for (int j = 0; j < 4; j++) s[i][j] = 0.0f;
#pragma unroll 8
        for (int z = 0; z < 64; z++) {
            float a[2], bb[4];
            a[0] = Qq[ty][z];
            a[1] = Qq[ty + 16][z];
#pragma unroll
            for (int j = 0; j < 4; j++) bb[j] = Kt[tx + j*16][z];
#pragma unroll
            for (int i = 0; i < 2; i++)
#pragma unroll
                for (int j = 0; j < 4; j++) s[i][j] += a[i] * bb[j];
        }
#pragma unroll
        for (int i = 0; i < 2; i++) {
            int q = ty + i * 16;
            float mq = ms[q], iq = ils[q];
#pragma unroll
            for (int j = 0; j < 4; j++)
                Ps[q][tx + j*16] = __expf(s[i][j] * SCALE - mq) * iq;
        }
        __syncthreads();

        // accumulate P^T K and P^T Q : thread owns t = ty+i*16, z = tx+j*16
#pragma unroll 4
        for (int q = 0; q < 32; q++) {
            float p[4], kv[4], qv[4];
#pragma unroll
            for (int i = 0; i < 4; i++) p[i] = Ps[q][ty + i*16];
#pragma unroll
            for (int j = 0; j < 4; j++) { kv[j] = Kq[q][tx + j*16]; qv[j] = Qq[q][tx + j*16]; }
#pragma unroll
            for (int i = 0; i < 4; i++)
#pragma unroll
                for (int j = 0; j < 4; j++) {
                    ck[i][j] += p[i] * kv[j];
                    cq[i][j] += p[i] * qv[j];
                }
        }
        __syncthreads();
    }

    float* CkB = g_Ck + (size_t)b * NN * CC + h * ZZ;
    float* CqB = g_Cq + (size_t)b * NN * CC + h * ZZ;
#pragma unroll
    for (int i = 0; i < 4; i++)
#pragma unroll
        for (int j = 0; j < 4; j++) {
            int t = t0 + ty + i * 16, z = tx + j * 16;
            CkB[(size_t)t * CC + z] = ck[i][j];
            CqB[(size_t)t * CC + z] = cq[i][j];
        }
}

// =============================================================================
// host
// =============================================================================
extern "C" void kernel_launch(void* const* d_in, const int* in_sizes, int n_in,
                              void* d_out, int out_size)
{
    (void)in_sizes; (void)n_in; (void)out_size;
    const float* x  = (const float*)d_in[0];
    const float* Wq = (const float*)d_in[1];
    const float* Wk = (const float*)d_in[2];
    const float* Wp = (const float*)d_in[3];
    const float* bp = (const float*)d_in[4];
    float* out = (float*)d_out;

    float *pQ, *pK, *pU1, *pU2, *pCk, *pCq;
    cudaGetSymbolAddress((void**)&pQ,  g_Q);
    cudaGetSymbolAddress((void**)&pK,  g_K);
    cudaGetSymbolAddress((void**)&pU1, g_U1);
    cudaGetSymbolAddress((void**)&pU2, g_U2);
    cudaGetSymbolAddress((void**)&pCk, g_Ck);
    cudaGetSymbolAddress((void**)&pCq, g_Cq);

    // U1t = Wp * Wq^T, U2t = Wp * Wk^T   (tiny)
    gemm_abt64<<<dim3(CC/64, CC/64), 256>>>(Wp, Wq, pU1, CC, CC, CC);
    gemm_abt64<<<dim3(CC/64, CC/64), 256>>>(Wp, Wk, pU2, CC, CC, CC);
    // Q = x Wq^T, K = x Wk^T
    gemm_abt128<<<dim3(BB*NN/128, CC/128), 256>>>(x, Wq, pQ, BB*NN, CC, CC);
    gemm_abt128<<<dim3(BB*NN/128, CC/128), 256>>>(x, Wk, pK, BB*NN, CC, CC);
    // softmax stats
    attn_stats<<<dim3(NN/64, BH), 256>>>();
    // Ck = A^T K, Cq = A^T Q
    attn_pass<<<dim3(NN/64, BH), 256>>>();
    // out = Ck U1t^T + Cq U2t^T + bp
    gemm_dual128<<<dim3(BB*NN/128, CC/128), 256>>>(pCk, pU1, pCq, pU2, bp, out,
                                                   BB*NN, CC, CC);
}